// round 14
// baseline (speedup 1.0000x reference)
#include <cuda_runtime.h>
#include <cuda_fp16.h>
#include <math.h>
#include <stdint.h>

#define T_TOK 1024
#define HDIM  1024
#define IDIM  512
#define NEXP  64
#define TOPK  8

// ================= scratch (static device globals; no allocation) =================
__device__ int   g_count[NEXP];
__device__ int   g_assign_tok[NEXP * T_TOK];
__device__ float g_assign_w[NEXP * T_TOK];
__device__ int   g_tok2slot[T_TOK * TOPK];
__device__ __half g_xh[T_TOK * HDIM];
__device__ __half g_sact[T_TOK * IDIM];
__device__ __half g_act[(size_t)NEXP * T_TOK * IDIM];
__device__ float g_part[(size_t)NEXP * T_TOK * HDIM];
// pre-converted fp16 weights
__device__ __half g_weg[(size_t)NEXP * HDIM * IDIM];
__device__ __half g_weu[(size_t)NEXP * HDIM * IDIM];
__device__ __half g_wed[(size_t)NEXP * IDIM * HDIM];
__device__ __half g_wsg[HDIM * IDIM];
__device__ __half g_wsu[HDIM * IDIM];
__device__ __half g_wsd[IDIM * HDIM];

// ================= primitives =================
__device__ __forceinline__ uint32_t smem_u32(const void* p) {
    uint32_t a;
    asm("{ .reg .u64 t; cvta.to.shared.u64 t, %1; cvt.u32.u64 %0, t; }" : "=r"(a) : "l"(p));
    return a;
}
__device__ __forceinline__ void ldsm4(uint32_t* r, uint32_t a) {
    asm volatile("ldmatrix.sync.aligned.m8n8.x4.shared.b16 {%0,%1,%2,%3}, [%4];"
                 : "=r"(r[0]), "=r"(r[1]), "=r"(r[2]), "=r"(r[3]) : "r"(a));
}
__device__ __forceinline__ void ldsm4t(uint32_t* r, uint32_t a) {
    asm volatile("ldmatrix.sync.aligned.m8n8.x4.trans.shared.b16 {%0,%1,%2,%3}, [%4];"
                 : "=r"(r[0]), "=r"(r[1]), "=r"(r[2]), "=r"(r[3]) : "r"(a));
}
__device__ __forceinline__ void mma16816(float* c, const uint32_t* a, const uint32_t* b) {
    asm volatile(
        "mma.sync.aligned.m16n8k16.row.col.f32.f16.f16.f32 "
        "{%0,%1,%2,%3}, {%4,%5,%6,%7}, {%8,%9}, {%0,%1,%2,%3};"
        : "+f"(c[0]), "+f"(c[1]), "+f"(c[2]), "+f"(c[3])
        : "r"(a[0]), "r"(a[1]), "r"(a[2]), "r"(a[3]), "r"(b[0]), "r"(b[1]));
}
__device__ __forceinline__ void cpa16(uint32_t dst, const void* src) {
    asm volatile("cp.async.ca.shared.global [%0], [%1], 16;" :: "r"(dst), "l"(src));
}
#define CP_COMMIT() asm volatile("cp.async.commit_group;" ::: "memory")
#define CP_WAIT0()  asm volatile("cp.async.wait_group 0;"  ::: "memory")
#define CP_WAIT1()  asm volatile("cp.async.wait_group 1;"  ::: "memory")

// ================= layout =================
#define PITCH    144
#define PITCH2   272
#define A_BYTES  (128 * PITCH)            // 18432
#define B_BYTES  (64 * PITCH)             // 9216
#define B2_BYTES (64 * PITCH2)            // 17408
#define GU_STAGE (A_BYTES + 2 * B_BYTES)  // 36864
#define DN_STAGE (A_BYTES + B2_BYTES)     // 35840
#define GU_SMEM  (2 * GU_STAGE)           // 73728
#define DN_SMEM  (2 * DN_STAGE)           // 71680

// ================= weight fp32 -> fp16 conversion =================
__global__ void cvt_kernel(const float* __restrict__ s, __half* __restrict__ d) {
    const size_t i = ((size_t)blockIdx.x * 256 + threadIdx.x) * 8;
    const float4 v0 = *(const float4*)(s + i);
    const float4 v1 = *(const float4*)(s + i + 4);
    __half2 p0 = __floats2half2_rn(v0.x, v0.y);
    __half2 p1 = __floats2half2_rn(v0.z, v0.w);
    __half2 p2 = __floats2half2_rn(v1.x, v1.y);
    __half2 p3 = __floats2half2_rn(v1.z, v1.w);
    *(uint4*)(d + i) = make_uint4(*(uint32_t*)&p0, *(uint32_t*)&p1,
                                  *(uint32_t*)&p2, *(uint32_t*)&p3);
}

// ================= init / router =================
__global__ void zero_counts_kernel() {
    if (threadIdx.x < NEXP) g_count[threadIdx.x] = 0;
}

// 8 tokens per block, 256 threads: e = tid&63, seg = tid>>6 (4 segs of 256 h).
// Each thread loads one rw value per h and FMAs into 8 per-token accumulators.
// Partial-sum structure (4 segs of 256) identical to prior round -> bit-identical routing.
__global__ void router_kernel(const float* __restrict__ x, const float* __restrict__ rw) {
    __shared__ float xs[HDIM * 8];        // transposed: xs[h*8 + t], 32KB
    __shared__ float partial[4][NEXP][8];
    __shared__ float aff[8][NEXP];
    const int tok0 = blockIdx.x * 8;
    const int tid = threadIdx.x; // 256

    // load 8 token rows, transpose into xs[h][t]
    for (int v = tid; v < 2048; v += 256) {
        const int t = v >> 8;          // 0..7
        const int h4 = (v & 255) * 4;  // 0..1020
        const float4 r = *(const float4*)(x + (size_t)(tok0 + t) * HDIM + h4);
        xs[(h4 + 0) * 8 + t] = r.x;
        xs[(h4 + 1) * 8 + t] = r.y;
        xs[(h4 + 2) * 8 + t] = r.z;
        xs[(h4 + 3) * 8 + t] = r.w;
    }
    __syncthreads();

    const int e = tid & 63;
    const int seg = tid >> 6;
    const int h0 = seg * 256;
    float acc[8] = {};
#pragma unroll 4
    for (int h = 0; h < 256; h++) {
        const float w = rw[(h0 + h) * NEXP + e];
        const float4 x0 = *(const float4*)(xs + (h0 + h) * 8);
        const float4 x1 = *(const float4*)(xs + (h0 + h) * 8 + 4);
        acc[0] += x0.x * w; acc[1] += x0.y * w; acc[2] += x0.z * w; acc[3] += x0.w * w;
        acc[4] += x1.x * w; acc[5] += x1.y * w; acc[6] += x1.z * w; acc[7] += x1.w * w;
    }
#pragma unroll
    for (int t = 0; t < 8; t++) partial[seg][e][t] = acc[t];
    __syncthreads();

    for (int idx = tid; idx < 512; idx += 256) {
        const int t = idx >> 6, ee = idx & 63;
        const float s = partial[0][ee][t] + partial[1][ee][t]
                      + partial[2][ee][t] + partial[3][ee][t];
        aff[t][ee] = 1.f / (1.f + expf(-s));
    }
    __syncthreads();

    if (tid < 8) {
        const int t = tok0 + tid;
        float tmp[NEXP];
#pragma unroll
        for (int i = 0; i < NEXP; i++) tmp[i] = aff[tid][i];
        int idx[TOPK]; float sc[TOPK]; float s = 0.f;
        for (int k = 0; k < TOPK; k++) {
            int bi = 0; float bv = -1e30f;
            for (int i = 0; i < NEXP; i++) if (tmp[i] > bv) { bv = tmp[i]; bi = i; }
            idx[k] = bi; sc[k] = bv; tmp[bi] = -1e30f; s += bv;
        }
        const float inv = 1.f / (s + 1e-9f);
        for (int k = 0; k < TOPK; k++) {
            const int e2 = idx[k];
            const int slot = atomicAdd(&g_count[e2], 1);
            g_assign_tok[e2 * T_TOK + slot] = t;
            g_assign_w[e2 * T_TOK + slot]   = sc[k] * inv;
            g_tok2slot[t * TOPK + k]        = e2 * T_TOK + slot;
        }
    }
}

// x -> fp16
__global__ void splitx_kernel(const float* __restrict__ x) {
    const int i = (blockIdx.x * 256 + threadIdx.x) * 8;
    const float4 v0 = *(const float4*)(x + i);
    const float4 v1 = *(const float4*)(x + i + 4);
    __half2 p0 = __floats2half2_rn(v0.x, v0.y);
    __half2 p1 = __floats2half2_rn(v0.z, v0.w);
    __half2 p2 = __floats2half2_rn(v1.x, v1.y);
    __half2 p3 = __floats2half2_rn(v1.z, v1.w);
    *(uint4*)(g_xh + i) = make_uint4(*(uint32_t*)&p0, *(uint32_t*)&p1,
                                     *(uint32_t*)&p2, *(uint32_t*)&p3);
}

// ================= fused gate/up GEMM (fp16, double-buffered cp.async) =====
__global__ __launch_bounds__(256, 2) void gateup_kernel()
{
    extern __shared__ __align__(16) char dyn[];
    __shared__ int toks[128];

    const int e = blockIdx.z;
    const bool shared_e = (e == NEXP);
    const int n0 = blockIdx.x * 64;
    const int row0 = blockIdx.y * 128;
    const int n = shared_e ? T_TOK : g_count[e];
    if (row0 >= n) return;

    const int tid = threadIdx.x;
    const int wid = tid >> 5, lane = tid & 31;
    const int wm = wid >> 1, wn = wid & 1;

    if (tid < 128) {
        const int r = row0 + tid;
        toks[tid] = shared_e ? r : ((r < n) ? g_assign_tok[e * T_TOK + r] : 0);
    }
    __syncthreads();

    const __half* WG = shared_e ? g_wsg : (g_weg + (size_t)e * HDIM * IDIM);
    const __half* WU = shared_e ? g_wsu : (g_weu + (size_t)e * HDIM * IDIM);

    const uint32_t uBase = smem_u32(dyn);

    const int arow = tid >> 1, aseg = tid & 1;
    const size_t aBase = (size_t)toks[arow] * HDIM + aseg * 32;
    const uint32_t aDst = (uint32_t)(arow * PITCH + aseg * 64);
    const int brow = tid >> 2, bq = tid & 3;
    const size_t bBase = (size_t)brow * IDIM + n0 + bq * 16;
    const uint32_t bDst = (uint32_t)(brow * PITCH + bq * 32);

    float gacc[2][4][4] = {};
    float uacc[2][4][4] = {};

#define GU_ISSUE(S, BUF)                                                            \
    {                                                                               \
        const int k0_ = (S) * 64;                                                   \
        const uint32_t ub = uBase + (BUF) * GU_STAGE;                               \
        const size_t ab = aBase + k0_;                                              \
        _Pragma("unroll")                                                           \
        for (int q = 0; q < 4; q++)                                                 \
            cpa16(ub + aDst + q * 16, g_xh + ab + q * 8);                           \
        const size_t bb = bBase + (size_t)k0_ * IDIM;                               \
        cpa16(ub + A_BYTES + bDst,                WG + bb);                         \
        cpa16(ub + A_BYTES + bDst + 16,           WG + bb + 8);                     \
        cpa16(ub + A_BYTES + B_BYTES + bDst,      WU + bb);                         \
        cpa16(ub + A_BYTES + B_BYTES + bDst + 16, WU + bb + 8);                     \
        CP_COMMIT();                                                                \
    }

    GU_ISSUE(0, 0);

    for (int s = 0; s < HDIM / 64; s++) {
        const int cur = s & 1;
        if (s + 1 < HDIM / 64) {
            GU_ISSUE(s + 1, cur ^ 1);
            CP_WAIT1();
        } else {
            CP_WAIT0();
        }
        __syncthreads();

        const uint32_t uAh = uBase + cur * GU_STAGE;
        const uint32_t uBg = uAh + A_BYTES;
        const uint32_t uBu = uBg + B_BYTES;

#pragma unroll
        for (int ks = 0; ks < 4; ks++) {
            uint32_t af[2][4];
#pragma unroll
            for (int mi = 0; mi < 2; mi++) {
                const uint32_t aoff = (uint32_t)((wm * 32 + mi * 16 + (lane & 15)) * PITCH
                                                 + ks * 32 + (lane >> 4) * 16);
                ldsm4(af[mi], uAh + aoff);
            }
#pragma unroll
            for (int p = 0; p < 2; p++) {
                const uint32_t boff = (uint32_t)((ks * 16 + (lane & 15)) * PITCH
                                                 + (wn * 32 + p * 16 + (lane >> 4) * 8) * 2);
                uint32_t bg[4], bu[4];
                ldsm4t(bg, uBg + boff);
                ldsm4t(bu, uBu + boff);
#pragma unroll
                for (int mi = 0; mi < 2; mi++) {
                    mma16816(gacc[mi][2 * p],     af[mi], bg);
                    mma16816(gacc[mi][2 * p + 1], af[mi], bg + 2);
                    mma16816(uacc[mi][2 * p],     af[mi], bu);
                    mma16816(uacc[mi][2 * p + 1], af[mi], bu + 2);
                }
            }
        }
        __syncthreads();
    }

    // epilogue: act = silu(g)*u*w -> fp16
    int nn = n - row0; if (nn > 128) nn = 128;
#pragma unroll
    for (int mi = 0; mi < 2; mi++) {
#pragma unroll
        for (int p = 0; p < 2; p++) {
            const int m = wm * 32 + mi * 16 + (lane >> 2) + p * 8;
            if (m >= nn) continue;
            float w = 1.f;
            __half* dh;
            if (shared_e) {
                dh = g_sact + (size_t)(row0 + m) * IDIM;
            } else {
                w = g_assign_w[e * T_TOK + row0 + m];
                dh = g_act + ((size_t)e * T_TOK + row0 + m) * IDIM;
            }
            const int ncb = n0 + wn * 32 + (lane & 3) * 2;
#pragma unroll
            for (int ni = 0; ni < 4; ni++) {
                const float g0 = gacc[mi][ni][p * 2 + 0];
                const float g1 = gacc[mi][ni][p * 2 + 1];
                const float u0 = uacc[mi][ni][p * 2 + 0];
                const float u1 = uacc[mi][ni][p * 2 + 1];
                const float a0 = g0 / (1.f + __expf(-g0)) * u0 * w;
                const float a1 = g1 / (1.f + __expf(-g1)) * u1 * w;
                __half2 h = __floats2half2_rn(a0, a1);
                *(uint32_t*)(dh + ncb + ni * 8) = *(uint32_t*)&h;
            }
        }
    }
}

// ================= down GEMM (fp16, N-tile 128, double-buffered cp.async) ====
__global__ __launch_bounds__(256, 2) void down_kernel(float* __restrict__ out)
{
    extern __shared__ __align__(16) char dyn[];

    const int e = blockIdx.z;
    const bool shared_e = (e == NEXP);
    const int n0 = blockIdx.x * 128;
    const int row0 = blockIdx.y * 128;
    const int n = shared_e ? T_TOK : g_count[e];
    if (row0 >= n) return;

    const int tid = threadIdx.x;
    const int wid = tid >> 5, lane = tid & 31;
    const int wm = wid >> 2, wn = wid & 3;   // 2 x 4 warps, warp tile 64x32

    const __half* W = shared_e ? g_wsd : (g_wed + (size_t)e * IDIM * HDIM);
    const __half* Ap = shared_e ? (g_sact + (size_t)row0 * IDIM)
                                : (g_act + ((size_t)e * T_TOK + row0) * IDIM);

    const uint32_t uBase = smem_u32(dyn);

    const int arow = tid >> 1, aseg = tid & 1;
    const size_t aBase = (size_t)arow * IDIM + aseg * 32;
    const uint32_t aDst = (uint32_t)(arow * PITCH + aseg * 64);
    const int brow = tid >> 2, bq = tid & 3;
    const size_t bBase = (size_t)brow * HDIM + n0 + bq * 32;
    const uint32_t bDst = (uint32_t)(brow * PITCH2 + bq * 64);

    float acc[4][4][4] = {};

#define DN_ISSUE(S, BUF)                                                            \
    {                                                                               \
        const int k0_ = (S) * 64;                                                   \
        const uint32_t ub = uBase + (BUF) * DN_STAGE;                               \
        const size_t ab = aBase + k0_;                                              \
        _Pragma("unroll")                                                           \
        for (int q = 0; q < 4; q++)                                                 \
            cpa16(ub + aDst + q * 16, Ap + ab + q * 8);                             \
        const size_t bb = bBase + (size_t)k0_ * HDIM;                               \
        _Pragma("unroll")                                                           \
        for (int q = 0; q < 4; q++)                                                 \
            cpa16(ub + A_BYTES + bDst + q * 16, W + bb + q * 8);                    \
        CP_COMMIT();                                                                \
    }

    DN_ISSUE(0, 0);

    for (int s = 0; s < IDIM / 64; s++) {
        const int cur = s & 1;
        if (s + 1 < IDIM / 64) {
            DN_ISSUE(s + 1, cur ^ 1);
            CP_WAIT1();
        } else {
            CP_WAIT0();
        }
        __syncthreads();

        const uint32_t uAh = uBase + cur * DN_STAGE;
        const uint32_t uB = uAh + A_BYTES;

#pragma unroll
        for (int ks = 0; ks < 4; ks++) {
            uint32_t af[4][4];
#pragma unroll
            for (int mi = 0; mi < 4; mi++) {
                const uint32_t aoff = (uint32_t)((wm * 64 + mi * 16 + (lane & 15)) * PITCH
                                                 + ks * 32 + (lane >> 4) * 16);
                ldsm4(af[mi], uAh + aoff);
            }
#pragma unroll
            for (int p = 0; p < 2; p++) {
                const uint32_t boff = (uint32_t)((ks * 16 + (lane & 15)) * PITCH2
                                                 + (wn * 32 + p * 16 + (lane >> 4) * 8) * 2);
                uint32_t b[4];
                ldsm4t(b, uB + boff);
#pragma unroll
                for (int mi = 0; mi < 4; mi++) {
                    mma16816(acc[mi][2 * p],     af[mi], b);
                    mma16816(acc[mi][2 * p + 1], af[mi], b + 2);
                }
            }
        }
        __syncthreads();
    }

#pragma unroll
    for (int mi = 0; mi < 4; mi++) {
#pragma unroll
        for (int p = 0; p < 2; p++) {
            const int m = wm * 64 + mi * 16 + (lane >> 2) + p * 8;
            float* dst = shared_e ? (out + (size_t)(row0 + m) * HDIM)
                                  : (g_part + ((size_t)e * T_TOK + row0 + m) * HDIM);
            const int ncb = n0 + wn * 32 + (lane & 3) * 2;
#pragma unroll
            for (int ni = 0; ni < 4; ni++) {
                float2 o = make_float2(acc[mi][ni][p * 2 + 0], acc[mi][ni][p * 2 + 1]);
                *(float2*)(dst + ncb + ni * 8) = o;
            }
        }
    }
}

// ================= gather =================
__global__ void gather_kernel(float* __restrict__ out) {
    __shared__ int slots[TOPK];
    const int t = blockIdx.x;
    if (threadIdx.x < TOPK) slots[threadIdx.x] = g_tok2slot[t * TOPK + threadIdx.x];
    __syncthreads();
    const int h = threadIdx.x * 4;
    float4 acc = *(float4*)(out + (size_t)t * HDIM + h);
#pragma unroll
    for (int k = 0; k < TOPK; k++) {
        const float4 p = *(const float4*)(g_part + (size_t)slots[k] * HDIM + h);
        acc.x += p.x; acc.y += p.y; acc.z += p.z; acc.w += p.w;
    }
    *(float4*)(out + (size_t)t * HDIM + h) = acc;
}

// ================= launch (multi-stream fork-join, graph-capturable) =================
extern "C" void kernel_launch(void* const* d_in, const int* in_sizes, int n_in,
                              void* d_out, int out_size) {
    const float* x  = (const float*)d_in[0];
    const float* rw = (const float*)d_in[1];
    const float* sg = (const float*)d_in[2];
    const float* su = (const float*)d_in[3];
    const float* sd = (const float*)d_in[4];
    const float* eg = (const float*)d_in[5];
    const float* eu = (const float*)d_in[6];
    const float* ed = (const float*)d_in[7];
    float* out = (float*)d_out;

    static cudaStream_t s2 = nullptr, s3 = nullptr;
    static cudaEvent_t evFork = nullptr, evJ2 = nullptr, evJ3 = nullptr, evMainCvt = nullptr;
    if (s2 == nullptr) {
        cudaStreamCreateWithFlags(&s2, cudaStreamNonBlocking);
        cudaStreamCreateWithFlags(&s3, cudaStreamNonBlocking);
        cudaEventCreateWithFlags(&evFork, cudaEventDisableTiming);
        cudaEventCreateWithFlags(&evJ2,  cudaEventDisableTiming);
        cudaEventCreateWithFlags(&evJ3,  cudaEventDisableTiming);
        cudaEventCreateWithFlags(&evMainCvt, cudaEventDisableTiming);
        cudaFuncSetAttribute(gateup_kernel, cudaFuncAttributeMaxDynamicSharedMemorySize, GU_SMEM);
        cudaFuncSetAttribute(down_kernel,   cudaFuncAttributeMaxDynamicSharedMemorySize, DN_SMEM);
    }

    __half *weg, *weu, *wed, *wsg, *wsu, *wsd;
    cudaGetSymbolAddress((void**)&weg, g_weg);
    cudaGetSymbolAddress((void**)&weu, g_weu);
    cudaGetSymbolAddress((void**)&wed, g_wed);
    cudaGetSymbolAddress((void**)&wsg, g_wsg);
    cudaGetSymbolAddress((void**)&wsu, g_wsu);
    cudaGetSymbolAddress((void**)&wsd, g_wsd);

    const int nb_e = (NEXP * HDIM * IDIM) / (256 * 8);   // 16384
    const int nb_s = (HDIM * IDIM) / (256 * 8);          // 256

    // fork
    cudaEventRecord(evFork, 0);
    cudaStreamWaitEvent(s2, evFork, 0);
    cudaStreamWaitEvent(s3, evFork, 0);

    // s3: routing + activation conversion (feeds gateup)
    zero_counts_kernel<<<1, 64, 0, s3>>>();
    router_kernel<<<T_TOK / 8, 256, 0, s3>>>(x, rw);
    splitx_kernel<<<(T_TOK * HDIM) / (256 * 8), 256, 0, s3>>>(x);
    cudaEventRecord(evJ3, s3);

    // main: gate/up weight conversion (full bandwidth; ed/sd deferred)
    cvt_kernel<<<nb_e, 256>>>(eg, weg);
    cvt_kernel<<<nb_e, 256>>>(eu, weu);
    cvt_kernel<<<nb_s, 256>>>(sg, wsg);
    cvt_kernel<<<nb_s, 256>>>(su, wsu);
    cudaEventRecord(evMainCvt, 0);

    // s2: down-weights convert AFTER gateup prerequisites, overlapping gateup
    cudaStreamWaitEvent(s2, evMainCvt, 0);
    cvt_kernel<<<nb_e, 256, 0, s2>>>(ed, wed);
    cvt_kernel<<<nb_s, 256, 0, s2>>>(sd, wsd);
    cudaEventRecord(evJ2, s2);

    cudaStreamWaitEvent(0, evJ3, 0);
    gateup_kernel<<<dim3(IDIM / 64, T_TOK / 128, NEXP + 1), 256, GU_SMEM>>>();
    cudaStreamWaitEvent(0, evJ2, 0);
    down_kernel<<<dim3(HDIM / 128, T_TOK / 128, NEXP + 1), 256, DN_SMEM>>>(out);
    gather_kernel<<<T_TOK, 256>>>(out);
}

// round 15
// speedup vs baseline: 1.4067x; 1.4067x over previous
#include <cuda_runtime.h>
#include <cuda_fp16.h>
#include <math.h>
#include <stdint.h>

#define T_TOK 1024
#define HDIM  1024
#define IDIM  512
#define NEXP  64
#define TOPK  8

// ================= scratch (static device globals; no allocation) =================
__device__ int   g_count[NEXP];
__device__ int   g_assign_tok[NEXP * T_TOK];
__device__ float g_assign_w[NEXP * T_TOK];
__device__ int   g_tok2slot[T_TOK * TOPK];
__device__ __half g_xh[T_TOK * HDIM];
__device__ __half g_sact[T_TOK * IDIM];
__device__ __half g_act[(size_t)NEXP * T_TOK * IDIM];
__device__ float g_part[(size_t)NEXP * T_TOK * HDIM];
// pre-converted fp16 weights
__device__ __half g_weg[(size_t)NEXP * HDIM * IDIM];
__device__ __half g_weu[(size_t)NEXP * HDIM * IDIM];
__device__ __half g_wed[(size_t)NEXP * IDIM * HDIM];
__device__ __half g_wsg[HDIM * IDIM];
__device__ __half g_wsu[HDIM * IDIM];
__device__ __half g_wsd[IDIM * HDIM];

// ================= primitives =================
__device__ __forceinline__ uint32_t smem_u32(const void* p) {
    uint32_t a;
    asm("{ .reg .u64 t; cvta.to.shared.u64 t, %1; cvt.u32.u64 %0, t; }" : "=r"(a) : "l"(p));
    return a;
}
__device__ __forceinline__ void ldsm4(uint32_t* r, uint32_t a) {
    asm volatile("ldmatrix.sync.aligned.m8n8.x4.shared.b16 {%0,%1,%2,%3}, [%4];"
                 : "=r"(r[0]), "=r"(r[1]), "=r"(r[2]), "=r"(r[3]) : "r"(a));
}
__device__ __forceinline__ void ldsm4t(uint32_t* r, uint32_t a) {
    asm volatile("ldmatrix.sync.aligned.m8n8.x4.trans.shared.b16 {%0,%1,%2,%3}, [%4];"
                 : "=r"(r[0]), "=r"(r[1]), "=r"(r[2]), "=r"(r[3]) : "r"(a));
}
__device__ __forceinline__ void mma16816(float* c, const uint32_t* a, const uint32_t* b) {
    asm volatile(
        "mma.sync.aligned.m16n8k16.row.col.f32.f16.f16.f32 "
        "{%0,%1,%2,%3}, {%4,%5,%6,%7}, {%8,%9}, {%0,%1,%2,%3};"
        : "+f"(c[0]), "+f"(c[1]), "+f"(c[2]), "+f"(c[3])
        : "r"(a[0]), "r"(a[1]), "r"(a[2]), "r"(a[3]), "r"(b[0]), "r"(b[1]));
}
__device__ __forceinline__ void cpa16(uint32_t dst, const void* src) {
    asm volatile("cp.async.ca.shared.global [%0], [%1], 16;" :: "r"(dst), "l"(src));
}
#define CP_COMMIT() asm volatile("cp.async.commit_group;" ::: "memory")
#define CP_WAIT0()  asm volatile("cp.async.wait_group 0;"  ::: "memory")
#define CP_WAIT1()  asm volatile("cp.async.wait_group 1;"  ::: "memory")

// ================= layout =================
#define PITCH    144
#define PITCH2   272
#define A_BYTES  (128 * PITCH)            // 18432
#define B_BYTES  (64 * PITCH)             // 9216
#define B2_BYTES (64 * PITCH2)            // 17408
#define GU_STAGE (A_BYTES + 2 * B_BYTES)  // 36864
#define DN_STAGE (A_BYTES + B2_BYTES)     // 35840
#define GU_SMEM  (2 * GU_STAGE)           // 73728
#define DN_SMEM  (2 * DN_STAGE)           // 71680

// ================= weight fp32 -> fp16 conversion =================
__global__ void cvt_kernel(const float* __restrict__ s, __half* __restrict__ d) {
    const size_t i = ((size_t)blockIdx.x * 256 + threadIdx.x) * 8;
    const float4 v0 = *(const float4*)(s + i);
    const float4 v1 = *(const float4*)(s + i + 4);
    __half2 p0 = __floats2half2_rn(v0.x, v0.y);
    __half2 p1 = __floats2half2_rn(v0.z, v0.w);
    __half2 p2 = __floats2half2_rn(v1.x, v1.y);
    __half2 p3 = __floats2half2_rn(v1.z, v1.w);
    *(uint4*)(d + i) = make_uint4(*(uint32_t*)&p0, *(uint32_t*)&p1,
                                  *(uint32_t*)&p2, *(uint32_t*)&p3);
}

// ================= init / router =================
__global__ void zero_counts_kernel() {
    if (threadIdx.x < NEXP) g_count[threadIdx.x] = 0;
}

// 8 tokens per block, 256 threads: e = tid&63, seg = tid>>6 (4 segs of 256 h).
__global__ void router_kernel(const float* __restrict__ x, const float* __restrict__ rw) {
    __shared__ float xs[HDIM * 8];        // transposed: xs[h*8 + t], 32KB
    __shared__ float partial[4][NEXP][8];
    __shared__ float aff[8][NEXP];
    const int tok0 = blockIdx.x * 8;
    const int tid = threadIdx.x; // 256

    for (int v = tid; v < 2048; v += 256) {
        const int t = v >> 8;
        const int h4 = (v & 255) * 4;
        const float4 r = *(const float4*)(x + (size_t)(tok0 + t) * HDIM + h4);
        xs[(h4 + 0) * 8 + t] = r.x;
        xs[(h4 + 1) * 8 + t] = r.y;
        xs[(h4 + 2) * 8 + t] = r.z;
        xs[(h4 + 3) * 8 + t] = r.w;
    }
    __syncthreads();

    const int e = tid & 63;
    const int seg = tid >> 6;
    const int h0 = seg * 256;
    float acc[8] = {};
#pragma unroll 4
    for (int h = 0; h < 256; h++) {
        const float w = rw[(h0 + h) * NEXP + e];
        const float4 x0 = *(const float4*)(xs + (h0 + h) * 8);
        const float4 x1 = *(const float4*)(xs + (h0 + h) * 8 + 4);
        acc[0] += x0.x * w; acc[1] += x0.y * w; acc[2] += x0.z * w; acc[3] += x0.w * w;
        acc[4] += x1.x * w; acc[5] += x1.y * w; acc[6] += x1.z * w; acc[7] += x1.w * w;
    }
#pragma unroll
    for (int t = 0; t < 8; t++) partial[seg][e][t] = acc[t];
    __syncthreads();

    for (int idx = tid; idx < 512; idx += 256) {
        const int t = idx >> 6, ee = idx & 63;
        const float s = partial[0][ee][t] + partial[1][ee][t]
                      + partial[2][ee][t] + partial[3][ee][t];
        aff[t][ee] = 1.f / (1.f + expf(-s));
    }
    __syncthreads();

    if (tid < 8) {
        const int t = tok0 + tid;
        float tmp[NEXP];
#pragma unroll
        for (int i = 0; i < NEXP; i++) tmp[i] = aff[tid][i];
        int idx[TOPK]; float sc[TOPK]; float s = 0.f;
        for (int k = 0; k < TOPK; k++) {
            int bi = 0; float bv = -1e30f;
            for (int i = 0; i < NEXP; i++) if (tmp[i] > bv) { bv = tmp[i]; bi = i; }
            idx[k] = bi; sc[k] = bv; tmp[bi] = -1e30f; s += bv;
        }
        const float inv = 1.f / (s + 1e-9f);
        for (int k = 0; k < TOPK; k++) {
            const int e2 = idx[k];
            const int slot = atomicAdd(&g_count[e2], 1);
            g_assign_tok[e2 * T_TOK + slot] = t;
            g_assign_w[e2 * T_TOK + slot]   = sc[k] * inv;
            g_tok2slot[t * TOPK + k]        = e2 * T_TOK + slot;
        }
    }
}

// x -> fp16
__global__ void splitx_kernel(const float* __restrict__ x) {
    const int i = (blockIdx.x * 256 + threadIdx.x) * 8;
    const float4 v0 = *(const float4*)(x + i);
    const float4 v1 = *(const float4*)(x + i + 4);
    __half2 p0 = __floats2half2_rn(v0.x, v0.y);
    __half2 p1 = __floats2half2_rn(v0.z, v0.w);
    __half2 p2 = __floats2half2_rn(v1.x, v1.y);
    __half2 p3 = __floats2half2_rn(v1.z, v1.w);
    *(uint4*)(g_xh + i) = make_uint4(*(uint32_t*)&p0, *(uint32_t*)&p1,
                                     *(uint32_t*)&p2, *(uint32_t*)&p3);
}

// ================= fused gate/up GEMM (fp16, double-buffered cp.async) =====
__global__ __launch_bounds__(256, 2) void gateup_kernel()
{
    extern __shared__ __align__(16) char dyn[];
    __shared__ int toks[128];

    const int e = blockIdx.z;
    const bool shared_e = (e == NEXP);
    const int n0 = blockIdx.x * 64;
    const int row0 = blockIdx.y * 128;
    const int n = shared_e ? T_TOK : g_count[e];
    if (row0 >= n) return;

    const int tid = threadIdx.x;
    const int wid = tid >> 5, lane = tid & 31;
    const int wm = wid >> 1, wn = wid & 1;

    if (tid < 128) {
        const int r = row0 + tid;
        toks[tid] = shared_e ? r : ((r < n) ? g_assign_tok[e * T_TOK + r] : 0);
    }
    __syncthreads();

    const __half* WG = shared_e ? g_wsg : (g_weg + (size_t)e * HDIM * IDIM);
    const __half* WU = shared_e ? g_wsu : (g_weu + (size_t)e * HDIM * IDIM);

    const uint32_t uBase = smem_u32(dyn);

    const int arow = tid >> 1, aseg = tid & 1;
    const size_t aBase = (size_t)toks[arow] * HDIM + aseg * 32;
    const uint32_t aDst = (uint32_t)(arow * PITCH + aseg * 64);
    const int brow = tid >> 2, bq = tid & 3;
    const size_t bBase = (size_t)brow * IDIM + n0 + bq * 16;
    const uint32_t bDst = (uint32_t)(brow * PITCH + bq * 32);

    float gacc[2][4][4] = {};
    float uacc[2][4][4] = {};

#define GU_ISSUE(S, BUF)                                                            \
    {                                                                               \
        const int k0_ = (S) * 64;                                                   \
        const uint32_t ub = uBase + (BUF) * GU_STAGE;                               \
        const size_t ab = aBase + k0_;                                              \
        _Pragma("unroll")                                                           \
        for (int q = 0; q < 4; q++)                                                 \
            cpa16(ub + aDst + q * 16, g_xh + ab + q * 8);                           \
        const size_t bb = bBase + (size_t)k0_ * IDIM;                               \
        cpa16(ub + A_BYTES + bDst,                WG + bb);                         \
        cpa16(ub + A_BYTES + bDst + 16,           WG + bb + 8);                     \
        cpa16(ub + A_BYTES + B_BYTES + bDst,      WU + bb);                         \
        cpa16(ub + A_BYTES + B_BYTES + bDst + 16, WU + bb + 8);                     \
        CP_COMMIT();                                                                \
    }

    GU_ISSUE(0, 0);

    for (int s = 0; s < HDIM / 64; s++) {
        const int cur = s & 1;
        if (s + 1 < HDIM / 64) {
            GU_ISSUE(s + 1, cur ^ 1);
            CP_WAIT1();
        } else {
            CP_WAIT0();
        }
        __syncthreads();

        const uint32_t uAh = uBase + cur * GU_STAGE;
        const uint32_t uBg = uAh + A_BYTES;
        const uint32_t uBu = uBg + B_BYTES;

#pragma unroll
        for (int ks = 0; ks < 4; ks++) {
            uint32_t af[2][4];
#pragma unroll
            for (int mi = 0; mi < 2; mi++) {
                const uint32_t aoff = (uint32_t)((wm * 32 + mi * 16 + (lane & 15)) * PITCH
                                                 + ks * 32 + (lane >> 4) * 16);
                ldsm4(af[mi], uAh + aoff);
            }
#pragma unroll
            for (int p = 0; p < 2; p++) {
                const uint32_t boff = (uint32_t)((ks * 16 + (lane & 15)) * PITCH
                                                 + (wn * 32 + p * 16 + (lane >> 4) * 8) * 2);
                uint32_t bg[4], bu[4];
                ldsm4t(bg, uBg + boff);
                ldsm4t(bu, uBu + boff);
#pragma unroll
                for (int mi = 0; mi < 2; mi++) {
                    mma16816(gacc[mi][2 * p],     af[mi], bg);
                    mma16816(gacc[mi][2 * p + 1], af[mi], bg + 2);
                    mma16816(uacc[mi][2 * p],     af[mi], bu);
                    mma16816(uacc[mi][2 * p + 1], af[mi], bu + 2);
                }
            }
        }
        __syncthreads();
    }

    // epilogue: act = silu(g)*u*w -> fp16
    int nn = n - row0; if (nn > 128) nn = 128;
#pragma unroll
    for (int mi = 0; mi < 2; mi++) {
#pragma unroll
        for (int p = 0; p < 2; p++) {
            const int m = wm * 32 + mi * 16 + (lane >> 2) + p * 8;
            if (m >= nn) continue;
            float w = 1.f;
            __half* dh;
            if (shared_e) {
                dh = g_sact + (size_t)(row0 + m) * IDIM;
            } else {
                w = g_assign_w[e * T_TOK + row0 + m];
                dh = g_act + ((size_t)e * T_TOK + row0 + m) * IDIM;
            }
            const int ncb = n0 + wn * 32 + (lane & 3) * 2;
#pragma unroll
            for (int ni = 0; ni < 4; ni++) {
                const float g0 = gacc[mi][ni][p * 2 + 0];
                const float g1 = gacc[mi][ni][p * 2 + 1];
                const float u0 = uacc[mi][ni][p * 2 + 0];
                const float u1 = uacc[mi][ni][p * 2 + 1];
                const float a0 = g0 / (1.f + __expf(-g0)) * u0 * w;
                const float a1 = g1 / (1.f + __expf(-g1)) * u1 * w;
                __half2 h = __floats2half2_rn(a0, a1);
                *(uint32_t*)(dh + ncb + ni * 8) = *(uint32_t*)&h;
            }
        }
    }
}

// ================= down GEMM (fp16, N-tile 128, double-buffered cp.async) ====
__global__ __launch_bounds__(256, 2) void down_kernel(float* __restrict__ out)
{
    extern __shared__ __align__(16) char dyn[];

    const int e = blockIdx.z;
    const bool shared_e = (e == NEXP);
    const int n0 = blockIdx.x * 128;
    const int row0 = blockIdx.y * 128;
    const int n = shared_e ? T_TOK : g_count[e];
    if (row0 >= n) return;

    const int tid = threadIdx.x;
    const int wid = tid >> 5, lane = tid & 31;
    const int wm = wid >> 2, wn = wid & 3;   // 2 x 4 warps, warp tile 64x32

    const __half* W = shared_e ? g_wsd : (g_wed + (size_t)e * IDIM * HDIM);
    const __half* Ap = shared_e ? (g_sact + (size_t)row0 * IDIM)
                                : (g_act + ((size_t)e * T_TOK + row0) * IDIM);

    const uint32_t uBase = smem_u32(dyn);

    const int arow = tid >> 1, aseg = tid & 1;
    const size_t aBase = (size_t)arow * IDIM + aseg * 32;
    const uint32_t aDst = (uint32_t)(arow * PITCH + aseg * 64);
    const int brow = tid >> 2, bq = tid & 3;
    const size_t bBase = (size_t)brow * HDIM + n0 + bq * 32;
    const uint32_t bDst = (uint32_t)(brow * PITCH2 + bq * 64);

    float acc[4][4][4] = {};

#define DN_ISSUE(S, BUF)                                                            \
    {                                                                               \
        const int k0_ = (S) * 64;                                                   \
        const uint32_t ub = uBase + (BUF) * DN_STAGE;                               \
        const size_t ab = aBase + k0_;                                              \
        _Pragma("unroll")                                                           \
        for (int q = 0; q < 4; q++)                                                 \
            cpa16(ub + aDst + q * 16, Ap + ab + q * 8);                             \
        const size_t bb = bBase + (size_t)k0_ * HDIM;                               \
        _Pragma("unroll")                                                           \
        for (int q = 0; q < 4; q++)                                                 \
            cpa16(ub + A_BYTES + bDst + q * 16, W + bb + q * 8);                    \
        CP_COMMIT();                                                                \
    }

    DN_ISSUE(0, 0);

    for (int s = 0; s < IDIM / 64; s++) {
        const int cur = s & 1;
        if (s + 1 < IDIM / 64) {
            DN_ISSUE(s + 1, cur ^ 1);
            CP_WAIT1();
        } else {
            CP_WAIT0();
        }
        __syncthreads();

        const uint32_t uAh = uBase + cur * DN_STAGE;
        const uint32_t uB = uAh + A_BYTES;

#pragma unroll
        for (int ks = 0; ks < 4; ks++) {
            uint32_t af[4][4];
#pragma unroll
            for (int mi = 0; mi < 4; mi++) {
                const uint32_t aoff = (uint32_t)((wm * 64 + mi * 16 + (lane & 15)) * PITCH
                                                 + ks * 32 + (lane >> 4) * 16);
                ldsm4(af[mi], uAh + aoff);
            }
#pragma unroll
            for (int p = 0; p < 2; p++) {
                const uint32_t boff = (uint32_t)((ks * 16 + (lane & 15)) * PITCH2
                                                 + (wn * 32 + p * 16 + (lane >> 4) * 8) * 2);
                uint32_t b[4];
                ldsm4t(b, uB + boff);
#pragma unroll
                for (int mi = 0; mi < 4; mi++) {
                    mma16816(acc[mi][2 * p],     af[mi], b);
                    mma16816(acc[mi][2 * p + 1], af[mi], b + 2);
                }
            }
        }
        __syncthreads();
    }

#pragma unroll
    for (int mi = 0; mi < 4; mi++) {
#pragma unroll
        for (int p = 0; p < 2; p++) {
            const int m = wm * 64 + mi * 16 + (lane >> 2) + p * 8;
            float* dst = shared_e ? (out + (size_t)(row0 + m) * HDIM)
                                  : (g_part + ((size_t)e * T_TOK + row0 + m) * HDIM);
            const int ncb = n0 + wn * 32 + (lane & 3) * 2;
#pragma unroll
            for (int ni = 0; ni < 4; ni++) {
                float2 o = make_float2(acc[mi][ni][p * 2 + 0], acc[mi][ni][p * 2 + 1]);
                *(float2*)(dst + ncb + ni * 8) = o;
            }
        }
    }
}

// ================= gather =================
__global__ void gather_kernel(float* __restrict__ out) {
    __shared__ int slots[TOPK];
    const int t = blockIdx.x;
    if (threadIdx.x < TOPK) slots[threadIdx.x] = g_tok2slot[t * TOPK + threadIdx.x];
    __syncthreads();
    const int h = threadIdx.x * 4;
    float4 acc = *(float4*)(out + (size_t)t * HDIM + h);
#pragma unroll
    for (int k = 0; k < TOPK; k++) {
        const float4 p = *(const float4*)(g_part + (size_t)slots[k] * HDIM + h);
        acc.x += p.x; acc.y += p.y; acc.z += p.z; acc.w += p.w;
    }
    *(float4*)(out + (size_t)t * HDIM + h) = acc;
}

// ================= launch (multi-stream fork-join, graph-capturable) =================
extern "C" void kernel_launch(void* const* d_in, const int* in_sizes, int n_in,
                              void* d_out, int out_size) {
    const float* x  = (const float*)d_in[0];
    const float* rw = (const float*)d_in[1];
    const float* sg = (const float*)d_in[2];
    const float* su = (const float*)d_in[3];
    const float* sd = (const float*)d_in[4];
    const float* eg = (const float*)d_in[5];
    const float* eu = (const float*)d_in[6];
    const float* ed = (const float*)d_in[7];
    float* out = (float*)d_out;

    static cudaStream_t s2 = nullptr, s3 = nullptr;
    static cudaEvent_t evFork = nullptr, evJ2 = nullptr, evJ3 = nullptr;
    if (s2 == nullptr) {
        cudaStreamCreateWithFlags(&s2, cudaStreamNonBlocking);
        cudaStreamCreateWithFlags(&s3, cudaStreamNonBlocking);
        cudaEventCreateWithFlags(&evFork, cudaEventDisableTiming);
        cudaEventCreateWithFlags(&evJ2,  cudaEventDisableTiming);
        cudaEventCreateWithFlags(&evJ3,  cudaEventDisableTiming);
        cudaFuncSetAttribute(gateup_kernel, cudaFuncAttributeMaxDynamicSharedMemorySize, GU_SMEM);
        cudaFuncSetAttribute(down_kernel,   cudaFuncAttributeMaxDynamicSharedMemorySize, DN_SMEM);
    }

    __half *weg, *weu, *wed, *wsg, *wsu, *wsd;
    cudaGetSymbolAddress((void**)&weg, g_weg);
    cudaGetSymbolAddress((void**)&weu, g_weu);
    cudaGetSymbolAddress((void**)&wed, g_wed);
    cudaGetSymbolAddress((void**)&wsg, g_wsg);
    cudaGetSymbolAddress((void**)&wsu, g_wsu);
    cudaGetSymbolAddress((void**)&wsd, g_wsd);

    const int nb_e = (NEXP * HDIM * IDIM) / (256 * 8);   // 16384
    const int nb_s = (HDIM * IDIM) / (256 * 8);          // 256

    // fork
    cudaEventRecord(evFork, 0);
    cudaStreamWaitEvent(s2, evFork, 0);
    cudaStreamWaitEvent(s3, evFork, 0);

    // s2: weights needed only by down_kernel (concurrent with main cvt phase)
    cvt_kernel<<<nb_e, 256, 0, s2>>>(ed, wed);
    cvt_kernel<<<nb_s, 256, 0, s2>>>(sd, wsd);
    cudaEventRecord(evJ2, s2);

    // s3: routing + activation conversion (feeds gateup)
    zero_counts_kernel<<<1, 64, 0, s3>>>();
    router_kernel<<<T_TOK / 8, 256, 0, s3>>>(x, rw);
    splitx_kernel<<<(T_TOK * HDIM) / (256 * 8), 256, 0, s3>>>(x);
    cudaEventRecord(evJ3, s3);

    // main: gate/up weight conversion (overlaps s2 + s3)
    cvt_kernel<<<nb_e, 256>>>(eg, weg);
    cvt_kernel<<<nb_e, 256>>>(eu, weu);
    cvt_kernel<<<nb_s, 256>>>(sg, wsg);
    cvt_kernel<<<nb_s, 256>>>(su, wsu);

    cudaStreamWaitEvent(0, evJ3, 0);
    gateup_kernel<<<dim3(IDIM / 64, T_TOK / 128, NEXP + 1), 256, GU_SMEM>>>();
    cudaStreamWaitEvent(0, evJ2, 0);
    down_kernel<<<dim3(HDIM / 128, T_TOK / 128, NEXP + 1), 256, DN_SMEM>>>(out);
    gather_kernel<<<T_TOK, 256>>>(out);
}

// round 16
// speedup vs baseline: 1.4535x; 1.0333x over previous
#include <cuda_runtime.h>
#include <cuda_fp16.h>
#include <math.h>
#include <stdint.h>

#define T_TOK 1024
#define HDIM  1024
#define IDIM  512
#define NEXP  64
#define TOPK  8

// ================= scratch (static device globals; no allocation) =================
__device__ int   g_count[NEXP];
__device__ int   g_assign_tok[NEXP * T_TOK];
__device__ float g_assign_w[NEXP * T_TOK];
__device__ int   g_tok2slot[T_TOK * TOPK];
__device__ __half g_xh[T_TOK * HDIM];
__device__ __half g_sact[T_TOK * IDIM];
__device__ __half g_act[(size_t)NEXP * T_TOK * IDIM];
__device__ float g_part[(size_t)NEXP * T_TOK * HDIM];
// pre-converted fp16 weights
__device__ __half g_weg[(size_t)NEXP * HDIM * IDIM];
__device__ __half g_weu[(size_t)NEXP * HDIM * IDIM];
__device__ __half g_wed[(size_t)NEXP * IDIM * HDIM];
__device__ __half g_wsg[HDIM * IDIM];
__device__ __half g_wsu[HDIM * IDIM];
__device__ __half g_wsd[IDIM * HDIM];

// ================= primitives =================
__device__ __forceinline__ uint32_t smem_u32(const void* p) {
    uint32_t a;
    asm("{ .reg .u64 t; cvta.to.shared.u64 t, %1; cvt.u32.u64 %0, t; }" : "=r"(a) : "l"(p));
    return a;
}
__device__ __forceinline__ void ldsm4(uint32_t* r, uint32_t a) {
    asm volatile("ldmatrix.sync.aligned.m8n8.x4.shared.b16 {%0,%1,%2,%3}, [%4];"
                 : "=r"(r[0]), "=r"(r[1]), "=r"(r[2]), "=r"(r[3]) : "r"(a));
}
__device__ __forceinline__ void ldsm4t(uint32_t* r, uint32_t a) {
    asm volatile("ldmatrix.sync.aligned.m8n8.x4.trans.shared.b16 {%0,%1,%2,%3}, [%4];"
                 : "=r"(r[0]), "=r"(r[1]), "=r"(r[2]), "=r"(r[3]) : "r"(a));
}
__device__ __forceinline__ void mma16816(float* c, const uint32_t* a, const uint32_t* b) {
    asm volatile(
        "mma.sync.aligned.m16n8k16.row.col.f32.f16.f16.f32 "
        "{%0,%1,%2,%3}, {%4,%5,%6,%7}, {%8,%9}, {%0,%1,%2,%3};"
        : "+f"(c[0]), "+f"(c[1]), "+f"(c[2]), "+f"(c[3])
        : "r"(a[0]), "r"(a[1]), "r"(a[2]), "r"(a[3]), "r"(b[0]), "r"(b[1]));
}
__device__ __forceinline__ void cpa16(uint32_t dst, const void* src) {
    asm volatile("cp.async.ca.shared.global [%0], [%1], 16;" :: "r"(dst), "l"(src));
}
#define CP_COMMIT() asm volatile("cp.async.commit_group;" ::: "memory")
#define CP_WAIT0()  asm volatile("cp.async.wait_group 0;"  ::: "memory")
#define CP_WAIT1()  asm volatile("cp.async.wait_group 1;"  ::: "memory")

// ================= layout =================
#define PITCH    144
#define PITCH2   272
#define A_BYTES  (128 * PITCH)            // 18432
#define B_BYTES  (64 * PITCH)             // 9216
#define B2_BYTES (64 * PITCH2)            // 17408
#define GU_STAGE (A_BYTES + 2 * B_BYTES)  // 36864
#define DN_STAGE (A_BYTES + B2_BYTES)     // 35840
#define GU_SMEM  (2 * GU_STAGE)           // 73728
#define DN_SMEM  (2 * DN_STAGE)           // 71680

// ================= weight fp32 -> fp16 conversion (3 tensors per launch) ==========
__global__ void cvt3_kernel(const float* __restrict__ s0, __half* __restrict__ d0,
                            const float* __restrict__ s1, __half* __restrict__ d1,
                            const float* __restrict__ s2, __half* __restrict__ d2) {
    const float* s = (blockIdx.y == 0) ? s0 : (blockIdx.y == 1) ? s1 : s2;
    __half*      d = (blockIdx.y == 0) ? d0 : (blockIdx.y == 1) ? d1 : d2;
    const size_t i = ((size_t)blockIdx.x * 256 + threadIdx.x) * 8;
    const float4 v0 = *(const float4*)(s + i);
    const float4 v1 = *(const float4*)(s + i + 4);
    __half2 p0 = __floats2half2_rn(v0.x, v0.y);
    __half2 p1 = __floats2half2_rn(v0.z, v0.w);
    __half2 p2 = __floats2half2_rn(v1.x, v1.y);
    __half2 p3 = __floats2half2_rn(v1.z, v1.w);
    *(uint4*)(d + i) = make_uint4(*(uint32_t*)&p0, *(uint32_t*)&p1,
                                  *(uint32_t*)&p2, *(uint32_t*)&p3);
}

// ================= init / router =================
__global__ void zero_counts_kernel() {
    if (threadIdx.x < NEXP) g_count[threadIdx.x] = 0;
}

// 2 tokens per block (512 blocks), 256 threads: e = tid&63, seg = tid>>6.
// Same 4-segment partial-sum order as before -> bit-identical routing.
__global__ void router_kernel(const float* __restrict__ x, const float* __restrict__ rw) {
    __shared__ float xs[HDIM * 2];        // transposed: xs[h*2 + t], 8KB
    __shared__ float partial[4][NEXP][2];
    __shared__ float aff[2][NEXP];
    const int tok0 = blockIdx.x * 2;
    const int tid = threadIdx.x; // 256

    {
        const int t = tid >> 7;          // 0..1
        const int h4 = (tid & 127) * 8;  // 0..1016
        const float4 r0 = *(const float4*)(x + (size_t)(tok0 + t) * HDIM + h4);
        const float4 r1 = *(const float4*)(x + (size_t)(tok0 + t) * HDIM + h4 + 4);
        xs[(h4 + 0) * 2 + t] = r0.x; xs[(h4 + 1) * 2 + t] = r0.y;
        xs[(h4 + 2) * 2 + t] = r0.z; xs[(h4 + 3) * 2 + t] = r0.w;
        xs[(h4 + 4) * 2 + t] = r1.x; xs[(h4 + 5) * 2 + t] = r1.y;
        xs[(h4 + 6) * 2 + t] = r1.z; xs[(h4 + 7) * 2 + t] = r1.w;
    }
    __syncthreads();

    const int e = tid & 63;
    const int seg = tid >> 6;
    const int h0 = seg * 256;
    float a0 = 0.f, a1 = 0.f;
#pragma unroll 8
    for (int h = 0; h < 256; h++) {
        const float w = rw[(h0 + h) * NEXP + e];
        const float2 xv = *(const float2*)(xs + (h0 + h) * 2);
        a0 += xv.x * w;
        a1 += xv.y * w;
    }
    partial[seg][e][0] = a0;
    partial[seg][e][1] = a1;
    __syncthreads();

    if (tid < 128) {
        const int t = tid >> 6, ee = tid & 63;
        const float s = partial[0][ee][t] + partial[1][ee][t]
                      + partial[2][ee][t] + partial[3][ee][t];
        aff[t][ee] = 1.f / (1.f + expf(-s));
    }
    __syncthreads();

    if (tid < 2) {
        const int t = tok0 + tid;
        float tmp[NEXP];
#pragma unroll
        for (int i = 0; i < NEXP; i++) tmp[i] = aff[tid][i];
        int idx[TOPK]; float sc[TOPK]; float s = 0.f;
        for (int k = 0; k < TOPK; k++) {
            int bi = 0; float bv = -1e30f;
            for (int i = 0; i < NEXP; i++) if (tmp[i] > bv) { bv = tmp[i]; bi = i; }
            idx[k] = bi; sc[k] = bv; tmp[bi] = -1e30f; s += bv;
        }
        const float inv = 1.f / (s + 1e-9f);
        for (int k = 0; k < TOPK; k++) {
            const int e2 = idx[k];
            const int slot = atomicAdd(&g_count[e2], 1);
            g_assign_tok[e2 * T_TOK + slot] = t;
            g_assign_w[e2 * T_TOK + slot]   = sc[k] * inv;
            g_tok2slot[t * TOPK + k]        = e2 * T_TOK + slot;
        }
    }
}

// x -> fp16
__global__ void splitx_kernel(const float* __restrict__ x) {
    const int i = (blockIdx.x * 256 + threadIdx.x) * 8;
    const float4 v0 = *(const float4*)(x + i);
    const float4 v1 = *(const float4*)(x + i + 4);
    __half2 p0 = __floats2half2_rn(v0.x, v0.y);
    __half2 p1 = __floats2half2_rn(v0.z, v0.w);
    __half2 p2 = __floats2half2_rn(v1.x, v1.y);
    __half2 p3 = __floats2half2_rn(v1.z, v1.w);
    *(uint4*)(g_xh + i) = make_uint4(*(uint32_t*)&p0, *(uint32_t*)&p1,
                                     *(uint32_t*)&p2, *(uint32_t*)&p3);
}

// ================= fused gate/up GEMM (fp16, double-buffered cp.async) =====
__global__ __launch_bounds__(256, 2) void gateup_kernel()
{
    extern __shared__ __align__(16) char dyn[];
    __shared__ int toks[128];

    const int e = blockIdx.z;
    const bool shared_e = (e == NEXP);
    const int n0 = blockIdx.x * 64;
    const int row0 = blockIdx.y * 128;
    const int n = shared_e ? T_TOK : g_count[e];
    if (row0 >= n) return;

    const int tid = threadIdx.x;
    const int wid = tid >> 5, lane = tid & 31;
    const int wm = wid >> 1, wn = wid & 1;

    if (tid < 128) {
        const int r = row0 + tid;
        toks[tid] = shared_e ? r : ((r < n) ? g_assign_tok[e * T_TOK + r] : 0);
    }
    __syncthreads();

    const __half* WG = shared_e ? g_wsg : (g_weg + (size_t)e * HDIM * IDIM);
    const __half* WU = shared_e ? g_wsu : (g_weu + (size_t)e * HDIM * IDIM);

    const uint32_t uBase = smem_u32(dyn);

    const int arow = tid >> 1, aseg = tid & 1;
    const size_t aBase = (size_t)toks[arow] * HDIM + aseg * 32;
    const uint32_t aDst = (uint32_t)(arow * PITCH + aseg * 64);
    const int brow = tid >> 2, bq = tid & 3;
    const size_t bBase = (size_t)brow * IDIM + n0 + bq * 16;
    const uint32_t bDst = (uint32_t)(brow * PITCH + bq * 32);

    float gacc[2][4][4] = {};
    float uacc[2][4][4] = {};

#define GU_ISSUE(S, BUF)                                                            \
    {                                                                               \
        const int k0_ = (S) * 64;                                                   \
        const uint32_t ub = uBase + (BUF) * GU_STAGE;                               \
        const size_t ab = aBase + k0_;                                              \
        _Pragma("unroll")                                                           \
        for (int q = 0; q < 4; q++)                                                 \
            cpa16(ub + aDst + q * 16, g_xh + ab + q * 8);                           \
        const size_t bb = bBase + (size_t)k0_ * IDIM;                               \
        cpa16(ub + A_BYTES + bDst,                WG + bb);                         \
        cpa16(ub + A_BYTES + bDst + 16,           WG + bb + 8);                     \
        cpa16(ub + A_BYTES + B_BYTES + bDst,      WU + bb);                         \
        cpa16(ub + A_BYTES + B_BYTES + bDst + 16, WU + bb + 8);                     \
        CP_COMMIT();                                                                \
    }

    GU_ISSUE(0, 0);

    for (int s = 0; s < HDIM / 64; s++) {
        const int cur = s & 1;
        if (s + 1 < HDIM / 64) {
            GU_ISSUE(s + 1, cur ^ 1);
            CP_WAIT1();
        } else {
            CP_WAIT0();
        }
        __syncthreads();

        const uint32_t uAh = uBase + cur * GU_STAGE;
        const uint32_t uBg = uAh + A_BYTES;
        const uint32_t uBu = uBg + B_BYTES;

#pragma unroll
        for (int ks = 0; ks < 4; ks++) {
            uint32_t af[2][4];
#pragma unroll
            for (int mi = 0; mi < 2; mi++) {
                const uint32_t aoff = (uint32_t)((wm * 32 + mi * 16 + (lane & 15)) * PITCH
                                                 + ks * 32 + (lane >> 4) * 16);
                ldsm4(af[mi], uAh + aoff);
            }
#pragma unroll
            for (int p = 0; p < 2; p++) {
                const uint32_t boff = (uint32_t)((ks * 16 + (lane & 15)) * PITCH
                                                 + (wn * 32 + p * 16 + (lane >> 4) * 8) * 2);
                uint32_t bg[4], bu[4];
                ldsm4t(bg, uBg + boff);
                ldsm4t(bu, uBu + boff);
#pragma unroll
                for (int mi = 0; mi < 2; mi++) {
                    mma16816(gacc[mi][2 * p],     af[mi], bg);
                    mma16816(gacc[mi][2 * p + 1], af[mi], bg + 2);
                    mma16816(uacc[mi][2 * p],     af[mi], bu);
                    mma16816(uacc[mi][2 * p + 1], af[mi], bu + 2);
                }
            }
        }
        __syncthreads();
    }

    // epilogue: act = silu(g)*u*w -> fp16
    int nn = n - row0; if (nn > 128) nn = 128;
#pragma unroll
    for (int mi = 0; mi < 2; mi++) {
#pragma unroll
        for (int p = 0; p < 2; p++) {
            const int m = wm * 32 + mi * 16 + (lane >> 2) + p * 8;
            if (m >= nn) continue;
            float w = 1.f;
            __half* dh;
            if (shared_e) {
                dh = g_sact + (size_t)(row0 + m) * IDIM;
            } else {
                w = g_assign_w[e * T_TOK + row0 + m];
                dh = g_act + ((size_t)e * T_TOK + row0 + m) * IDIM;
            }
            const int ncb = n0 + wn * 32 + (lane & 3) * 2;
#pragma unroll
            for (int ni = 0; ni < 4; ni++) {
                const float g0 = gacc[mi][ni][p * 2 + 0];
                const float g1 = gacc[mi][ni][p * 2 + 1];
                const float u0 = uacc[mi][ni][p * 2 + 0];
                const float u1 = uacc[mi][ni][p * 2 + 1];
                const float a0 = g0 / (1.f + __expf(-g0)) * u0 * w;
                const float a1 = g1 / (1.f + __expf(-g1)) * u1 * w;
                __half2 h = __floats2half2_rn(a0, a1);
                *(uint32_t*)(dh + ncb + ni * 8) = *(uint32_t*)&h;
            }
        }
    }
}

// ================= down GEMM (fp16, N-tile 128, double-buffered cp.async) ====
__global__ __launch_bounds__(256, 2) void down_kernel(float* __restrict__ out)
{
    extern __shared__ __align__(16) char dyn[];

    const int e = blockIdx.z;
    const bool shared_e = (e == NEXP);
    const int n0 = blockIdx.x * 128;
    const int row0 = blockIdx.y * 128;
    const int n = shared_e ? T_TOK : g_count[e];
    if (row0 >= n) return;

    const int tid = threadIdx.x;
    const int wid = tid >> 5, lane = tid & 31;
    const int wm = wid >> 2, wn = wid & 3;   // 2 x 4 warps, warp tile 64x32

    const __half* W = shared_e ? g_wsd : (g_wed + (size_t)e * IDIM * HDIM);
    const __half* Ap = shared_e ? (g_sact + (size_t)row0 * IDIM)
                                : (g_act + ((size_t)e * T_TOK + row0) * IDIM);

    const uint32_t uBase = smem_u32(dyn);

    const int arow = tid >> 1, aseg = tid & 1;
    const size_t aBase = (size_t)arow * IDIM + aseg * 32;
    const uint32_t aDst = (uint32_t)(arow * PITCH + aseg * 64);
    const int brow = tid >> 2, bq = tid & 3;
    const size_t bBase = (size_t)brow * HDIM + n0 + bq * 32;
    const uint32_t bDst = (uint32_t)(brow * PITCH2 + bq * 64);

    float acc[4][4][4] = {};

#define DN_ISSUE(S, BUF)                                                            \
    {                                                                               \
        const int k0_ = (S) * 64;                                                   \
        const uint32_t ub = uBase + (BUF) * DN_STAGE;                               \
        const size_t ab = aBase + k0_;                                              \
        _Pragma("unroll")                                                           \
        for (int q = 0; q < 4; q++)                                                 \
            cpa16(ub + aDst + q * 16, Ap + ab + q * 8);                             \
        const size_t bb = bBase + (size_t)k0_ * HDIM;                               \
        _Pragma("unroll")                                                           \
        for (int q = 0; q < 4; q++)                                                 \
            cpa16(ub + A_BYTES + bDst + q * 16, W + bb + q * 8);                    \
        CP_COMMIT();                                                                \
    }

    DN_ISSUE(0, 0);

    for (int s = 0; s < IDIM / 64; s++) {
        const int cur = s & 1;
        if (s + 1 < IDIM / 64) {
            DN_ISSUE(s + 1, cur ^ 1);
            CP_WAIT1();
        } else {
            CP_WAIT0();
        }
        __syncthreads();

        const uint32_t uAh = uBase + cur * DN_STAGE;
        const uint32_t uB = uAh + A_BYTES;

#pragma unroll
        for (int ks = 0; ks < 4; ks++) {
            uint32_t af[4][4];
#pragma unroll
            for (int mi = 0; mi < 4; mi++) {
                const uint32_t aoff = (uint32_t)((wm * 64 + mi * 16 + (lane & 15)) * PITCH
                                                 + ks * 32 + (lane >> 4) * 16);
                ldsm4(af[mi], uAh + aoff);
            }
#pragma unroll
            for (int p = 0; p < 2; p++) {
                const uint32_t boff = (uint32_t)((ks * 16 + (lane & 15)) * PITCH2
                                                 + (wn * 32 + p * 16 + (lane >> 4) * 8) * 2);
                uint32_t b[4];
                ldsm4t(b, uB + boff);
#pragma unroll
                for (int mi = 0; mi < 4; mi++) {
                    mma16816(acc[mi][2 * p],     af[mi], b);
                    mma16816(acc[mi][2 * p + 1], af[mi], b + 2);
                }
            }
        }
        __syncthreads();
    }

#pragma unroll
    for (int mi = 0; mi < 4; mi++) {
#pragma unroll
        for (int p = 0; p < 2; p++) {
            const int m = wm * 64 + mi * 16 + (lane >> 2) + p * 8;
            float* dst = shared_e ? (out + (size_t)(row0 + m) * HDIM)
                                  : (g_part + ((size_t)e * T_TOK + row0 + m) * HDIM);
            const int ncb = n0 + wn * 32 + (lane & 3) * 2;
#pragma unroll
            for (int ni = 0; ni < 4; ni++) {
                float2 o = make_float2(acc[mi][ni][p * 2 + 0], acc[mi][ni][p * 2 + 1]);
                *(float2*)(dst + ncb + ni * 8) = o;
            }
        }
    }
}

// ================= gather =================
__global__ void gather_kernel(float* __restrict__ out) {
    __shared__ int slots[TOPK];
    const int t = blockIdx.x;
    if (threadIdx.x < TOPK) slots[threadIdx.x] = g_tok2slot[t * TOPK + threadIdx.x];
    __syncthreads();
    const int h = threadIdx.x * 4;
    float4 acc = *(float4*)(out + (size_t)t * HDIM + h);
#pragma unroll
    for (int k = 0; k < TOPK; k++) {
        const float4 p = *(const float4*)(g_part + (size_t)slots[k] * HDIM + h);
        acc.x += p.x; acc.y += p.y; acc.z += p.z; acc.w += p.w;
    }
    *(float4*)(out + (size_t)t * HDIM + h) = acc;
}

// ================= launch (priority-stream fork-join, graph-capturable) ============
extern "C" void kernel_launch(void* const* d_in, const int* in_sizes, int n_in,
                              void* d_out, int out_size) {
    const float* x  = (const float*)d_in[0];
    const float* rw = (const float*)d_in[1];
    const float* sg = (const float*)d_in[2];
    const float* su = (const float*)d_in[3];
    const float* sd = (const float*)d_in[4];
    const float* eg = (const float*)d_in[5];
    const float* eu = (const float*)d_in[6];
    const float* ed = (const float*)d_in[7];
    float* out = (float*)d_out;

    static cudaStream_t s3 = nullptr;
    static cudaEvent_t evFork = nullptr, evJ3 = nullptr;
    if (s3 == nullptr) {
        int loPri, hiPri;
        cudaDeviceGetStreamPriorityRange(&loPri, &hiPri);
        cudaStreamCreateWithPriority(&s3, cudaStreamNonBlocking, hiPri);
        cudaEventCreateWithFlags(&evFork, cudaEventDisableTiming);
        cudaEventCreateWithFlags(&evJ3,  cudaEventDisableTiming);
        cudaFuncSetAttribute(gateup_kernel, cudaFuncAttributeMaxDynamicSharedMemorySize, GU_SMEM);
        cudaFuncSetAttribute(down_kernel,   cudaFuncAttributeMaxDynamicSharedMemorySize, DN_SMEM);
    }

    __half *weg, *weu, *wed, *wsg, *wsu, *wsd;
    cudaGetSymbolAddress((void**)&weg, g_weg);
    cudaGetSymbolAddress((void**)&weu, g_weu);
    cudaGetSymbolAddress((void**)&wed, g_wed);
    cudaGetSymbolAddress((void**)&wsg, g_wsg);
    cudaGetSymbolAddress((void**)&wsu, g_wsu);
    cudaGetSymbolAddress((void**)&wsd, g_wsd);

    const int nb_e = (NEXP * HDIM * IDIM) / (256 * 8);   // 16384
    const int nb_s = (HDIM * IDIM) / (256 * 8);          // 256

    // fork
    cudaEventRecord(evFork, 0);
    cudaStreamWaitEvent(s3, evFork, 0);

    // s3 (high priority): routing + activation conversion, scheduled ahead of cvt flood
    zero_counts_kernel<<<1, 64, 0, s3>>>();
    router_kernel<<<T_TOK / 2, 256, 0, s3>>>(x, rw);
    splitx_kernel<<<(T_TOK * HDIM) / (256 * 8), 256, 0, s3>>>(x);
    cudaEventRecord(evJ3, s3);

    // main: all weight conversions in 2 batched launches
    cvt3_kernel<<<dim3(nb_e, 3), 256>>>(eg, weg, eu, weu, ed, wed);
    cvt3_kernel<<<dim3(nb_s, 3), 256>>>(sg, wsg, su, wsu, sd, wsd);

    cudaStreamWaitEvent(0, evJ3, 0);
    gateup_kernel<<<dim3(IDIM / 64, T_TOK / 128, NEXP + 1), 256, GU_SMEM>>>();
    down_kernel<<<dim3(HDIM / 128, T_TOK / 128, NEXP + 1), 256, DN_SMEM>>>(out);
    gather_kernel<<<T_TOK, 256>>>(out);
}